// round 11
// baseline (speedup 1.0000x reference)
#include <cuda_runtime.h>
#include <cuda_fp16.h>
#include <math.h>

#define NB     2
#define SQ     2048
#define HIDDEN 1024
#define NHEAD  16
#define HDIM   64
#define SKVLEN 2048
#define TKV    4096
#define LOG2E  1.4426950408889634f

// half-precision staging buffers
__device__ __half d_xh[NB * SQ * HIDDEN];
__device__ __half d_wh[3 * HIDDEN * HIDDEN];
__device__ __half d_kvsh[2 * NB * NHEAD * SKVLEN * HDIM];
__device__ __half d_qh[NB * NHEAD * SQ * HDIM];   // pre-scaled by log2e/64
__device__ __half d_kh[NB * NHEAD * SQ * HDIM];
__device__ __half d_vh[NB * NHEAD * SQ * HDIM];

// split-attention partial outputs
__device__ float d_o0[NB * NHEAD * SQ * HDIM];
__device__ float d_o1[NB * NHEAD * SQ * HDIM];
__device__ float d_l0[NB * NHEAD * SQ];
__device__ float d_l1[NB * NHEAD * SQ];

// ---------------------------------------------------------------------------
// helpers
// ---------------------------------------------------------------------------
__device__ __forceinline__ void mma16816(float c[4], unsigned a0, unsigned a1,
                                         unsigned a2, unsigned a3,
                                         unsigned b0, unsigned b1) {
    asm volatile(
        "mma.sync.aligned.m16n8k16.row.col.f32.f16.f16.f32 "
        "{%0,%1,%2,%3},{%4,%5,%6,%7},{%8,%9},{%0,%1,%2,%3};"
        : "+f"(c[0]), "+f"(c[1]), "+f"(c[2]), "+f"(c[3])
        : "r"(a0), "r"(a1), "r"(a2), "r"(a3), "r"(b0), "r"(b1));
}
__device__ __forceinline__ void mma16816h(unsigned c[2], unsigned a0, unsigned a1,
                                          unsigned a2, unsigned a3,
                                          unsigned b0, unsigned b1) {
    asm volatile(
        "mma.sync.aligned.m16n8k16.row.col.f16.f16.f16.f16 "
        "{%0,%1},{%2,%3,%4,%5},{%6,%7},{%0,%1};"
        : "+r"(c[0]), "+r"(c[1])
        : "r"(a0), "r"(a1), "r"(a2), "r"(a3), "r"(b0), "r"(b1));
}
__device__ __forceinline__ void ldsm_x4(unsigned& r0, unsigned& r1,
                                        unsigned& r2, unsigned& r3, unsigned a) {
    asm volatile("ldmatrix.sync.aligned.m8n8.x4.shared.b16 {%0,%1,%2,%3},[%4];"
                 : "=r"(r0), "=r"(r1), "=r"(r2), "=r"(r3) : "r"(a));
}
__device__ __forceinline__ void ldsm_x4t(unsigned& r0, unsigned& r1,
                                         unsigned& r2, unsigned& r3, unsigned a) {
    asm volatile("ldmatrix.sync.aligned.m8n8.x4.trans.shared.b16 {%0,%1,%2,%3},[%4];"
                 : "=r"(r0), "=r"(r1), "=r"(r2), "=r"(r3) : "r"(a));
}
__device__ __forceinline__ void cp16(unsigned saddr, const void* g) {
    asm volatile("cp.async.cg.shared.global [%0],[%1],16;" :: "r"(saddr), "l"(g));
}
__device__ __forceinline__ void cp_commit() {
    asm volatile("cp.async.commit_group;" ::: "memory");
}
__device__ __forceinline__ void cp_wait0() {
    asm volatile("cp.async.wait_group 0;" ::: "memory");
}
__device__ __forceinline__ void cp_wait1() {
    asm volatile("cp.async.wait_group 1;" ::: "memory");
}
__device__ __forceinline__ unsigned ex2h2(unsigned x) {
    unsigned r;
    asm("ex2.approx.f16x2 %0, %1;" : "=r"(r) : "r"(x));
    return r;
}

// ---------------------------------------------------------------------------
// Fused fp32 -> fp16 conversion for all inputs, one launch.
// ---------------------------------------------------------------------------
#define XN4   (NB * SQ * HIDDEN / 4)
#define WN4   (HIDDEN * HIDDEN / 4)
#define KVN4  (2 * NB * NHEAD * SKVLEN * HDIM / 4)
#define TOTN4 (XN4 + 3 * WN4 + KVN4)

__global__ void cvt_all_kernel(const float* __restrict__ x,
                               const float* __restrict__ Wq,
                               const float* __restrict__ Wk,
                               const float* __restrict__ Wv,
                               const float* __restrict__ kvs,
                               const float* __restrict__ kvw) {
    int i = blockIdx.x * blockDim.x + threadIdx.x;
    if (i >= TOTN4) return;
    const float* src;
    __half2* dst;
    float s = 1.0f;
    int j = i;
    if (j < XN4) {
        src = x; dst = (__half2*)d_xh;
    } else if ((j -= XN4) < WN4) {
        src = Wq; dst = (__half2*)d_wh;
    } else if ((j -= WN4) < WN4) {
        src = Wk; dst = (__half2*)(d_wh + HIDDEN * HIDDEN);
    } else if ((j -= WN4) < WN4) {
        src = Wv; dst = (__half2*)(d_wh + 2 * HIDDEN * HIDDEN);
    } else {
        j -= WN4;
        src = kvs; dst = (__half2*)d_kvsh; s = kvw[0];
    }
    float4 v = reinterpret_cast<const float4*>(src)[j];
    dst[2 * j]     = __floats2half2_rn(v.x * s, v.y * s);
    dst[2 * j + 1] = __floats2half2_rn(v.z * s, v.w * s);
}

// ---------------------------------------------------------------------------
// QKV projection: y = x @ W^T + b.  fp16 mma, fp32 accum.
// grid = (64, 8, nz), z = zbase + blockIdx.z.  CTA tile m64 x n128 x k64 stage.
// 3-buffer cp.async ring, 2-stage lookahead (wait_group 1).
// ---------------------------------------------------------------------------
#define QKV_AB   9216
#define QKV_BB   18432
#define QKV_STEP (QKV_AB + QKV_BB)
#define QKV_SMEM (3 * QKV_STEP)            // 82944

__global__ __launch_bounds__(256, 2)
void qkv_kernel(const float* __restrict__ bq, const float* __restrict__ bk,
                const float* __restrict__ bv, int zbase)
{
    extern __shared__ __align__(16) __half sAB[];

    const int z = zbase + blockIdx.z;
    const __half* __restrict__ W = d_wh + (size_t)z * HIDDEN * HIDDEN;
    const float* __restrict__ bias = (z == 0) ? bq : (z == 1) ? bk : bv;
    __half* __restrict__ outp = (z == 0) ? d_qh : (z == 1) ? d_kh : d_vh;
    const float scl = (z == 0) ? (LOG2E / 64.0f) : 1.0f;

    const int m0 = blockIdx.x * 64;
    const int n0 = blockIdx.y * 128;
    const int tid = threadIdx.x, lane = tid & 31, w = tid >> 5;
    const int wm = w >> 1, wn = w & 1;
    const int l = lane;

    const unsigned sbase = (unsigned)__cvta_generic_to_shared(sAB);
    const unsigned aoffB = sbase + 2 * ((wm * 16 + (l & 15)) * 72 + (l >> 4) * 8);
    const unsigned boffB = sbase + QKV_AB +
        2 * ((wn * 64 + (l >> 4) * 8 + (l & 7)) * 72 + ((l >> 3) & 1) * 8);

    auto issue = [&](int ks, int buf) {
        int k0 = ks * 64;
        unsigned base = sbase + buf * QKV_STEP;
        #pragma unroll
        for (int u = 0; u < 2; u++) {
            int idx = tid + u * 256;
            int row = idx >> 3, c8 = idx & 7;
            cp16(base + (row * 72 + c8 * 8) * 2,
                 d_xh + (size_t)(m0 + row) * HIDDEN + k0 + c8 * 8);
        }
        #pragma unroll
        for (int u = 0; u < 4; u++) {
            int idx = tid + u * 256;
            int row = idx >> 3, c8 = idx & 7;
            cp16(base + QKV_AB + (row * 72 + c8 * 8) * 2,
                 W + (size_t)(n0 + row) * HIDDEN + k0 + c8 * 8);
        }
    };

    float acc[8][4] = {};

    issue(0, 0);
    cp_commit();
    issue(1, 1);
    cp_commit();

    for (int ks = 0; ks < 16; ks++) {
        int buf = ks - (ks / 3) * 3;
        if (ks < 15) cp_wait1(); else cp_wait0();
        __syncthreads();
        if (ks + 2 < 16) {
            int nb2 = (ks + 2) - ((ks + 2) / 3) * 3;
            issue(ks + 2, nb2);
            cp_commit();
        }

        unsigned bo = buf * QKV_STEP;
        #pragma unroll
        for (int kb = 0; kb < 4; kb++) {
            unsigned a0, a1, a2, a3;
            ldsm_x4(a0, a1, a2, a3, aoffB + bo + kb * 32);
            #pragma unroll
            for (int nbp = 0; nbp < 4; nbp++) {
                unsigned b0, b1, b2, b3;
                ldsm_x4(b0, b1, b2, b3, boffB + bo + nbp * 2304 + kb * 32);
                mma16816(acc[nbp * 2],     a0, a1, a2, a3, b0, b1);
                mma16816(acc[nbp * 2 + 1], a0, a1, a2, a3, b2, b3);
            }
        }
    }

    const int h = blockIdx.y * 2 + wn;
    const int mlo = m0 + wm * 16 + (lane >> 2);
    #pragma unroll
    for (int nb = 0; nb < 8; nb++) {
        int dcol = nb * 8 + 2 * (lane & 3);
        float2 bv2 = *(const float2*)&bias[h * 64 + dcol];
        __half2 h0 = __floats2half2_rn((acc[nb][0] + bv2.x) * scl,
                                       (acc[nb][1] + bv2.y) * scl);
        __half2 h1 = __floats2half2_rn((acc[nb][2] + bv2.x) * scl,
                                       (acc[nb][3] + bv2.y) * scl);
        int m1 = mlo, m2 = mlo + 8;
        *(__half2*)&outp[(((size_t)(m1 >> 11) * NHEAD + h) * SQ + (m1 & 2047)) * HDIM + dcol] = h0;
        *(__half2*)&outp[(((size_t)(m2 >> 11) * NHEAD + h) * SQ + (m2 & 2047)) * HDIM + dcol] = h1;
    }
}

// ---------------------------------------------------------------------------
// Flash attention (split): key stages [s0, s1) of 128 keys each; partial O + l.
// 3-buffer cp.async ring, 2-stage lookahead.
// grid = (16, 32), block = 256 (8 warps x m16 q-rows), q-tile 128.
// ---------------------------------------------------------------------------
#define AT_KB    18432
#define AT_STEP  (2 * AT_KB)
#define ATTN_SMEM (3 * AT_STEP)            // 110592

__global__ __launch_bounds__(256, 2)
void attn_kernel(int s0, int s1, int part)
{
    extern __shared__ __align__(16) __half sKV[];

    const int tid = threadIdx.x, lane = tid & 31, w = tid >> 5;
    const int r0 = lane >> 2, m4 = lane & 3;
    const int wq = w * 16;
    const int q0 = blockIdx.x * 128;
    const int bh = blockIdx.y;
    const int l = lane;
    const int NS = s1 - s0;

    const unsigned sbase = (unsigned)__cvta_generic_to_shared(sKV);
    const unsigned koffB = sbase + 2 * (((l >> 4) * 8 + (l & 7)) * 72 + ((l >> 3) & 1) * 8);
    const unsigned voffB = sbase + AT_KB +
        2 * ((((l >> 3) & 1) * 8 + (l & 7)) * 72 + (l >> 4) * 8);
    const unsigned ONES = 0x3C003C00u;

    // Q fragments (pre-scaled by log2e/64)
    unsigned qa[4][4];
    {
        const __half* qb = d_qh + ((size_t)bh * SQ + q0 + wq) * HDIM;
        #pragma unroll
        for (int kb = 0; kb < 4; kb++) {
            qa[kb][0] = *(const unsigned*)&qb[(r0    ) * 64 + kb * 16 + 2 * m4    ];
            qa[kb][1] = *(const unsigned*)&qb[(r0 + 8) * 64 + kb * 16 + 2 * m4    ];
            qa[kb][2] = *(const unsigned*)&qb[(r0    ) * 64 + kb * 16 + 2 * m4 + 8];
            qa[kb][3] = *(const unsigned*)&qb[(r0 + 8) * 64 + kb * 16 + 2 * m4 + 8];
        }
    }

    float oacc[8][4] = {};
    float lacc[4] = {};

    const __half* kB0 = d_kvsh + (size_t)bh * SKVLEN * HDIM;
    const __half* vB0 = d_kvsh + ((size_t)(NB * NHEAD) + bh) * SKVLEN * HDIM;
    const __half* kB1 = d_kh + (size_t)bh * SQ * HDIM;
    const __half* vB1 = d_vh + (size_t)bh * SQ * HDIM;

    auto issue = [&](int st, int buf) {
        int jg0 = st * 128;
        const __half *ks, *vs;
        if (jg0 < SKVLEN) { ks = kB0 + (size_t)jg0 * HDIM; vs = vB0 + (size_t)jg0 * HDIM; }
        else { int js = jg0 - SKVLEN; ks = kB1 + (size_t)js * HDIM; vs = vB1 + (size_t)js * HDIM; }
        unsigned base = sbase + buf * AT_STEP;
        #pragma unroll
        for (int u = 0; u < 4; u++) {
            int idx = tid + u * 256;
            int row = idx >> 3, c8 = idx & 7;
            unsigned dK = base + (row * 72 + c8 * 8) * 2;
            cp16(dK,         ks + row * 64 + c8 * 8);
            cp16(dK + AT_KB, vs + row * 64 + c8 * 8);
        }
    };

    issue(s0, 0);
    cp_commit();
    issue(s0 + 1, 1);
    cp_commit();

    for (int t = 0; t < NS; t++) {
        int buf = t - (t / 3) * 3;
        if (t < NS - 1) cp_wait1(); else cp_wait0();
        __syncthreads();
        if (t + 2 < NS) {
            int nb2 = (t + 2) - ((t + 2) / 3) * 3;
            issue(s0 + t + 2, nb2);
            cp_commit();
        }
        unsigned bo = buf * AT_STEP;

        #pragma unroll
        for (int sub = 0; sub < 2; sub++) {
            unsigned so = bo + sub * 9216;

            unsigned sc16[8][2];
            #pragma unroll
            for (int nb = 0; nb < 8; nb++) { sc16[nb][0] = 0u; sc16[nb][1] = 0u; }
            #pragma unroll
            for (int kb = 0; kb < 4; kb++) {
                #pragma unroll
                for (int nbp = 0; nbp < 4; nbp++) {
                    unsigned b0, b1, b2, b3;
                    ldsm_x4(b0, b1, b2, b3, koffB + so + nbp * 2304 + kb * 32);
                    mma16816h(sc16[nbp * 2],     qa[kb][0], qa[kb][1], qa[kb][2], qa[kb][3], b0, b1);
                    mma16816h(sc16[nbp * 2 + 1], qa[kb][0], qa[kb][1], qa[kb][2], qa[kb][3], b2, b3);
                }
            }

            unsigned pa[4][4];
            #pragma unroll
            for (int kb = 0; kb < 4; kb++) {
                pa[kb][0] = ex2h2(sc16[2 * kb][0]);
                pa[kb][1] = ex2h2(sc16[2 * kb][1]);
                pa[kb][2] = ex2h2(sc16[2 * kb + 1][0]);
                pa[kb][3] = ex2h2(sc16[2 * kb + 1][1]);
            }

            #pragma unroll
            for (int kb = 0; kb < 4; kb++) {
                mma16816(lacc, pa[kb][0], pa[kb][1], pa[kb][2], pa[kb][3], ONES, ONES);
                #pragma unroll
                for (int nbp = 0; nbp < 4; nbp++) {
                    unsigned b0, b1, b2, b3;
                    ldsm_x4t(b0, b1, b2, b3, voffB + so + kb * 2304 + nbp * 32);
                    mma16816(oacc[nbp * 2],     pa[kb][0], pa[kb][1], pa[kb][2], pa[kb][3], b0, b1);
                    mma16816(oacc[nbp * 2 + 1], pa[kb][0], pa[kb][1], pa[kb][2], pa[kb][3], b2, b3);
                }
            }
        }
    }

    // ---- partial epilogue ----
    float* op = part ? d_o1 : d_o0;
    float* lp = part ? d_l1 : d_l0;
    float* ob = op + ((size_t)bh * SQ + q0 + wq) * HDIM;
    #pragma unroll
    for (int nb = 0; nb < 8; nb++) {
        float2 v0 = {oacc[nb][0], oacc[nb][1]};
        float2 v1 = {oacc[nb][2], oacc[nb][3]};
        *(float2*)&ob[(r0    ) * HDIM + nb * 8 + 2 * m4] = v0;
        *(float2*)&ob[(r0 + 8) * HDIM + nb * 8 + 2 * m4] = v1;
    }
    if (m4 == 0) {
        lp[bh * SQ + q0 + wq + r0]     = lacc[0];
        lp[bh * SQ + q0 + wq + r0 + 8] = lacc[2];
    }
}

// ---------------------------------------------------------------------------
// Combine: out = (O0 + O1) / (l0 + l1), with [bh][q][d] -> [b][q][h*64+d]
// ---------------------------------------------------------------------------
__global__ void combine_kernel(float* __restrict__ out) {
    int i = blockIdx.x * blockDim.x + threadIdx.x;
    int d4 = i & 15;
    int q  = (i >> 4) & (SQ - 1);
    int bh = i >> 15;
    float4 a = ((const float4*)d_o0)[i];
    float4 b = ((const float4*)d_o1)[i];
    float inv = 1.0f / (d_l0[bh * SQ + q] + d_l1[bh * SQ + q]);
    float4 r;
    r.x = (a.x + b.x) * inv;
    r.y = (a.y + b.y) * inv;
    r.z = (a.z + b.z) * inv;
    r.w = (a.w + b.w) * inv;
    int bb = bh >> 4, h = bh & 15;
    ((float4*)out)[(size_t)(bb * SQ + q) * (HIDDEN / 4) + h * 16 + d4] = r;
}

// ---------------------------------------------------------------------------
extern "C" void kernel_launch(void* const* d_in, const int* in_sizes, int n_in,
                              void* d_out, int out_size)
{
    const float* x    = (const float*)d_in[0];
    const float* kvs  = (const float*)d_in[1];
    const float* Wq   = (const float*)d_in[2];
    const float* bq   = (const float*)d_in[3];
    const float* Wk   = (const float*)d_in[4];
    const float* bk   = (const float*)d_in[5];
    const float* Wv   = (const float*)d_in[6];
    const float* bv   = (const float*)d_in[7];
    const float* kvw  = (const float*)d_in[8];
    float* out = (float*)d_out;

    cudaFuncSetAttribute(qkv_kernel, cudaFuncAttributeMaxDynamicSharedMemorySize,
                         QKV_SMEM);
    cudaFuncSetAttribute(attn_kernel, cudaFuncAttributeMaxDynamicSharedMemorySize,
                         ATTN_SMEM);

    cudaStream_t s2;
    cudaStreamCreateWithFlags(&s2, cudaStreamNonBlocking);
    cudaEvent_t evC, evQ, evB;
    cudaEventCreateWithFlags(&evC, cudaEventDisableTiming);
    cudaEventCreateWithFlags(&evQ, cudaEventDisableTiming);
    cudaEventCreateWithFlags(&evB, cudaEventDisableTiming);

    // stream 0: conversions -> Q projection -> attention over kvs keys
    cvt_all_kernel<<<(TOTN4 + 255) / 256, 256>>>(x, Wq, Wk, Wv, kvs, kvw);
    cudaEventRecord(evC, 0);

    dim3 gq(NB * SQ / 64, NHEAD / 2, 1);
    qkv_kernel<<<gq, 256, QKV_SMEM>>>(bq, bk, bv, 0);
    cudaEventRecord(evQ, 0);

    dim3 g2(SQ / 128, NB * NHEAD);
    attn_kernel<<<g2, 256, ATTN_SMEM>>>(0, 16, 0);

    // stream s2: K/V projection -> attention over projected keys
    cudaStreamWaitEvent(s2, evC, 0);
    dim3 gkv(NB * SQ / 64, NHEAD / 2, 2);
    qkv_kernel<<<gkv, 256, QKV_SMEM, s2>>>(bq, bk, bv, 1);
    cudaStreamWaitEvent(s2, evQ, 0);
    attn_kernel<<<g2, 256, ATTN_SMEM, s2>>>(16, 32, 1);
    cudaEventRecord(evB, s2);

    // join and combine
    cudaStreamWaitEvent(0, evB, 0);
    combine_kernel<<<NB * NHEAD * SQ * HDIM / 4 / 256, 256>>>(out);
}

// round 12
// speedup vs baseline: 1.2038x; 1.2038x over previous
#include <cuda_runtime.h>
#include <cuda_fp16.h>
#include <math.h>

#define NB     2
#define SQ     2048
#define HIDDEN 1024
#define NHEAD  16
#define HDIM   64
#define SKVLEN 2048
#define TKV    4096
#define LOG2E  1.4426950408889634f

// half-precision staging buffers (pre-swizzled / tiled where noted)
__device__ __align__(1024) __half d_xh[NB * SQ * HIDDEN];      // [ks][m][64], SW128
__device__ __align__(1024) __half d_wh[3 * HIDDEN * HIDDEN];   // [z][ks][n][64], SW128
__device__ __align__(1024) __half d_kvsh[2 * NB * NHEAD * SKVLEN * HDIM]; // [2][bh][j][64], SW128
__device__ __align__(1024) __half d_qh[NB * NHEAD * SQ * HDIM];  // linear, pre-scaled log2e/64
__device__ __align__(1024) __half d_kh[NB * NHEAD * SQ * HDIM];  // [bh][s][64], SW128
__device__ __align__(1024) __half d_vh[NB * NHEAD * SQ * HDIM];  // [bh][s][64], SW128

// split-attention partial outputs
__device__ float d_o0[NB * NHEAD * SQ * HDIM];
__device__ float d_o1[NB * NHEAD * SQ * HDIM];
__device__ float d_l0[NB * NHEAD * SQ];
__device__ float d_l1[NB * NHEAD * SQ];

// ---------------------------------------------------------------------------
// helpers
// ---------------------------------------------------------------------------
__device__ __forceinline__ unsigned swz(unsigned b) { return b ^ ((b >> 3) & 0x70); }

__device__ __forceinline__ void mma16816(float c[4], unsigned a0, unsigned a1,
                                         unsigned a2, unsigned a3,
                                         unsigned b0, unsigned b1) {
    asm volatile(
        "mma.sync.aligned.m16n8k16.row.col.f32.f16.f16.f32 "
        "{%0,%1,%2,%3},{%4,%5,%6,%7},{%8,%9},{%0,%1,%2,%3};"
        : "+f"(c[0]), "+f"(c[1]), "+f"(c[2]), "+f"(c[3])
        : "r"(a0), "r"(a1), "r"(a2), "r"(a3), "r"(b0), "r"(b1));
}
__device__ __forceinline__ void mma16816h(unsigned c[2], unsigned a0, unsigned a1,
                                          unsigned a2, unsigned a3,
                                          unsigned b0, unsigned b1) {
    asm volatile(
        "mma.sync.aligned.m16n8k16.row.col.f16.f16.f16.f16 "
        "{%0,%1},{%2,%3,%4,%5},{%6,%7},{%0,%1};"
        : "+r"(c[0]), "+r"(c[1])
        : "r"(a0), "r"(a1), "r"(a2), "r"(a3), "r"(b0), "r"(b1));
}
__device__ __forceinline__ void ldsm_x4(unsigned& r0, unsigned& r1,
                                        unsigned& r2, unsigned& r3, unsigned a) {
    asm volatile("ldmatrix.sync.aligned.m8n8.x4.shared.b16 {%0,%1,%2,%3},[%4];"
                 : "=r"(r0), "=r"(r1), "=r"(r2), "=r"(r3) : "r"(a));
}
__device__ __forceinline__ void ldsm_x4t(unsigned& r0, unsigned& r1,
                                         unsigned& r2, unsigned& r3, unsigned a) {
    asm volatile("ldmatrix.sync.aligned.m8n8.x4.trans.shared.b16 {%0,%1,%2,%3},[%4];"
                 : "=r"(r0), "=r"(r1), "=r"(r2), "=r"(r3) : "r"(a));
}
__device__ __forceinline__ unsigned ex2h2(unsigned x) {
    unsigned r;
    asm("ex2.approx.f16x2 %0, %1;" : "=r"(r) : "r"(x));
    return r;
}
__device__ __forceinline__ void bulk_g2s(unsigned dst, const void* src,
                                         unsigned bytes, unsigned mbar) {
    asm volatile(
        "cp.async.bulk.shared::cluster.global.mbarrier::complete_tx::bytes "
        "[%0], [%1], %2, [%3];"
        :: "r"(dst), "l"(src), "r"(bytes), "r"(mbar) : "memory");
}
#define MBAR_INIT(mb, n) \
    asm volatile("mbarrier.init.shared.b64 [%0], %1;" :: "r"(mb), "r"((unsigned)(n)) : "memory")
#define MBAR_EXPECT_TX(mb, bytes) \
    asm volatile("mbarrier.arrive.expect_tx.shared.b64 _, [%0], %1;" \
                 :: "r"(mb), "r"((unsigned)(bytes)) : "memory")
#define MBAR_WAIT(mb, par) do { \
    unsigned _d; \
    asm volatile("{\n\t.reg .pred p;\n\t" \
        "mbarrier.try_wait.parity.acquire.cta.shared::cta.b64 p, [%1], %2;\n\t" \
        "selp.b32 %0, 1, 0, p;\n\t}" : "=r"(_d) : "r"(mb), "r"((unsigned)(par)) : "memory"); \
    if (!_d) { \
        asm volatile("{\n\t.reg .pred P1;\n\tWL_%=:\n\t" \
            "mbarrier.try_wait.parity.acquire.cta.shared::cta.b64 P1, [%0], %1, 0x989680;\n\t" \
            "@P1 bra.uni WD_%=;\n\tbra.uni WL_%=;\n\tWD_%=:\n\t}" \
            :: "r"(mb), "r"((unsigned)(par)) : "memory"); \
    } \
} while (0)

// ---------------------------------------------------------------------------
// Fused fp32 -> fp16 conversion.  Writes tiled + SW128-pre-swizzled layouts.
// ---------------------------------------------------------------------------
#define XN4   (NB * SQ * HIDDEN / 4)
#define WN4   (HIDDEN * HIDDEN / 4)
#define KVN4  (2 * NB * NHEAD * SKVLEN * HDIM / 4)
#define TOTN4 (XN4 + 3 * WN4 + KVN4)

__global__ void cvt_all_kernel(const float* __restrict__ x,
                               const float* __restrict__ Wq,
                               const float* __restrict__ Wk,
                               const float* __restrict__ Wv,
                               const float* __restrict__ kvs,
                               const float* __restrict__ kvw) {
    int i = blockIdx.x * blockDim.x + threadIdx.x;
    if (i >= TOTN4) return;
    int j = i;
    if (j < XN4) {
        // x[m][k] -> d_xh tile [ks][m][64]
        float4 v = reinterpret_cast<const float4*>(x)[j];
        int m = j >> 8, k4 = (j & 255) * 4;
        unsigned hidx = (unsigned)(k4 >> 6) * (NB * SQ * 64u) + (unsigned)m * 64 + (k4 & 63);
        unsigned b = swz(hidx * 2);
        char* p = (char*)d_xh;
        *(__half2*)(p + b)     = __floats2half2_rn(v.x, v.y);
        *(__half2*)(p + b + 4) = __floats2half2_rn(v.z, v.w);
    } else if ((j -= XN4) < 3 * WN4) {
        // W[n][k] -> d_wh tile [z][ks][n][64]
        int z = j / WN4;
        int jj = j - z * WN4;
        const float* W = (z == 0) ? Wq : (z == 1) ? Wk : Wv;
        float4 v = reinterpret_cast<const float4*>(W)[jj];
        int n = jj >> 8, k4 = (jj & 255) * 4;
        unsigned hidx = ((unsigned)(z * 16 + (k4 >> 6))) * 65536u + (unsigned)n * 64 + (k4 & 63);
        unsigned b = swz(hidx * 2);
        char* p = (char*)d_wh;
        *(__half2*)(p + b)     = __floats2half2_rn(v.x, v.y);
        *(__half2*)(p + b + 4) = __floats2half2_rn(v.z, v.w);
    } else {
        // kvs linear, swizzled in place, scaled by kvw
        j -= 3 * WN4;
        float s = kvw[0];
        float4 v = reinterpret_cast<const float4*>(kvs)[j];
        unsigned b = swz((unsigned)j * 8u);
        char* p = (char*)d_kvsh;
        *(__half2*)(p + b)     = __floats2half2_rn(v.x * s, v.y * s);
        *(__half2*)(p + b + 4) = __floats2half2_rn(v.z * s, v.w * s);
    }
}

// ---------------------------------------------------------------------------
// QKV projection: y = x @ W^T + b.  fp16 mma, fp32 accum, bulk-copy staging.
// grid = (64, 8, nz), z = zbase + blockIdx.z.  CTA tile m64 x n128 x k64 stage.
// smem: [2][ A 8KB | B 16KB ] + 2 mbarriers.
// ---------------------------------------------------------------------------
#define QKV_STEP 24576
#define QKV_MB   (2 * QKV_STEP)
#define QKV_SMEM (QKV_MB + 16)

__global__ __launch_bounds__(256, 2)
void qkv_kernel(const float* __restrict__ bq, const float* __restrict__ bk,
                const float* __restrict__ bv, int zbase)
{
    extern __shared__ __align__(128) char sm[];

    const int z = zbase + blockIdx.z;
    const float* __restrict__ bias = (z == 0) ? bq : (z == 1) ? bk : bv;
    const float scl = (z == 0) ? (LOG2E / 64.0f) : 1.0f;

    const int m0 = blockIdx.x * 64;
    const int n0 = blockIdx.y * 128;
    const int tid = threadIdx.x, lane = tid & 31, w = tid >> 5;
    const int wm = w >> 1, wn = w & 1;
    const int l = lane;

    unsigned sbase;
    asm("{ .reg .u64 t; cvta.to.shared.u64 t, %1; cvt.u32.u64 %0, t; }" : "=r"(sbase) : "l"(sm));
    const unsigned mb = sbase + QKV_MB;

    auto issue = [&](int ks, int buf) {
        unsigned d = sbase + buf * QKV_STEP;
        unsigned m = mb + buf * 8;
        MBAR_EXPECT_TX(m, QKV_STEP);
        bulk_g2s(d,        d_xh + ((size_t)ks * (NB * SQ) + m0) * 64, 8192, m);
        bulk_g2s(d + 8192, d_wh + (((size_t)z * 16 + ks) * 1024 + n0) * 64, 16384, m);
    };

    if (tid == 0) { MBAR_INIT(mb, 1); MBAR_INIT(mb + 8, 1); }
    __syncthreads();
    if (tid == 0) { issue(0, 0); issue(1, 1); }

    // per-thread logical fragment offsets (bytes within buffer; swz at use)
    const unsigned aB = (unsigned)(wm * 16 + (l & 15)) * 128 + (l >> 4) * 16;
    const unsigned bB = (unsigned)(wn * 64 + (l >> 4) * 8 + (l & 7)) * 128 + ((l >> 3) & 1) * 16;

    float acc[8][4] = {};

    for (int ks = 0; ks < 16; ks++) {
        int buf = ks & 1;
        MBAR_WAIT(mb + buf * 8, (ks >> 1) & 1);
        unsigned base = sbase + buf * QKV_STEP;

        #pragma unroll
        for (int kb = 0; kb < 4; kb++) {
            unsigned a0, a1, a2, a3;
            ldsm_x4(a0, a1, a2, a3, base + swz(aB + kb * 32));
            #pragma unroll
            for (int nbp = 0; nbp < 4; nbp++) {
                unsigned b0, b1, b2, b3;
                ldsm_x4(b0, b1, b2, b3, base + 8192 + swz(bB + nbp * 2048 + kb * 32));
                mma16816(acc[nbp * 2],     a0, a1, a2, a3, b0, b1);
                mma16816(acc[nbp * 2 + 1], a0, a1, a2, a3, b2, b3);
            }
        }
        __syncthreads();
        if (ks + 2 < 16 && tid == 0) issue(ks + 2, buf);
    }

    const int h = blockIdx.y * 2 + wn;
    const int mlo = m0 + wm * 16 + (lane >> 2);
    #pragma unroll
    for (int nb = 0; nb < 8; nb++) {
        int dcol = nb * 8 + 2 * (lane & 3);
        float2 bv2 = *(const float2*)&bias[h * 64 + dcol];
        __half2 h0 = __floats2half2_rn((acc[nb][0] + bv2.x) * scl,
                                       (acc[nb][1] + bv2.y) * scl);
        __half2 h1 = __floats2half2_rn((acc[nb][2] + bv2.x) * scl,
                                       (acc[nb][3] + bv2.y) * scl);
        int m1 = mlo, m2 = mlo + 8;
        if (z == 0) {
            *(__half2*)&d_qh[(((size_t)(m1 >> 11) * NHEAD + h) * SQ + (m1 & 2047)) * HDIM + dcol] = h0;
            *(__half2*)&d_qh[(((size_t)(m2 >> 11) * NHEAD + h) * SQ + (m2 & 2047)) * HDIM + dcol] = h1;
        } else {
            char* p = (char*)((z == 1) ? d_kh : d_vh);
            unsigned i1 = (((unsigned)(m1 >> 11) * NHEAD + h) * SQ + (m1 & 2047)) * 64 + dcol;
            unsigned i2 = (((unsigned)(m2 >> 11) * NHEAD + h) * SQ + (m2 & 2047)) * 64 + dcol;
            *(__half2*)(p + swz(i1 * 2)) = h0;
            *(__half2*)(p + swz(i2 * 2)) = h1;
        }
    }
}

// ---------------------------------------------------------------------------
// Flash attention (split): key stages [s0, s1) of 128 keys; bulk staging.
// grid = (16, 32), block = 256 (8 warps x m16 q-rows), q-tile 128.
// smem: [2][ K 16KB | V 16KB ] + 2 mbarriers.
// ---------------------------------------------------------------------------
#define AT_STEP  32768
#define AT_MB    (2 * AT_STEP)
#define ATTN_SMEM (AT_MB + 16)

__global__ __launch_bounds__(256, 2)
void attn_kernel(int s0, int s1, int part)
{
    extern __shared__ __align__(128) char sm[];

    const int tid = threadIdx.x, lane = tid & 31, w = tid >> 5;
    const int r0 = lane >> 2, m4 = lane & 3;
    const int wq = w * 16;
    const int q0 = blockIdx.x * 128;
    const int bh = blockIdx.y;
    const int l = lane;
    const int NS = s1 - s0;

    unsigned sbase;
    asm("{ .reg .u64 t; cvta.to.shared.u64 t, %1; cvt.u32.u64 %0, t; }" : "=r"(sbase) : "l"(sm));
    const unsigned mb = sbase + AT_MB;
    const unsigned ONES = 0x3C003C00u;

    // Q fragments (linear layout, pre-scaled by log2e/64)
    unsigned qa[4][4];
    {
        const __half* qb = d_qh + ((size_t)bh * SQ + q0 + wq) * HDIM;
        #pragma unroll
        for (int kb = 0; kb < 4; kb++) {
            qa[kb][0] = *(const unsigned*)&qb[(r0    ) * 64 + kb * 16 + 2 * m4    ];
            qa[kb][1] = *(const unsigned*)&qb[(r0 + 8) * 64 + kb * 16 + 2 * m4    ];
            qa[kb][2] = *(const unsigned*)&qb[(r0    ) * 64 + kb * 16 + 2 * m4 + 8];
            qa[kb][3] = *(const unsigned*)&qb[(r0 + 8) * 64 + kb * 16 + 2 * m4 + 8];
        }
    }

    auto issue = [&](int st, int buf) {
        const __half *ks_p, *vs_p;
        if (st < 16) {
            ks_p = d_kvsh + ((size_t)bh * SKVLEN + st * 128) * 64;
            vs_p = d_kvsh + ((size_t)(NB * NHEAD + bh) * SKVLEN + st * 128) * 64;
        } else {
            int js = (st - 16) * 128;
            ks_p = d_kh + ((size_t)bh * SQ + js) * 64;
            vs_p = d_vh + ((size_t)bh * SQ + js) * 64;
        }
        unsigned d = sbase + buf * AT_STEP;
        unsigned m = mb + buf * 8;
        MBAR_EXPECT_TX(m, AT_STEP);
        bulk_g2s(d,         ks_p, 16384, m);
        bulk_g2s(d + 16384, vs_p, 16384, m);
    };

    if (tid == 0) { MBAR_INIT(mb, 1); MBAR_INIT(mb + 8, 1); }
    __syncthreads();
    if (tid == 0) { issue(s0, 0); issue(s0 + 1, 1); }

    // per-thread logical fragment offsets
    const unsigned kB = (unsigned)((l >> 4) * 8 + (l & 7)) * 128 + ((l >> 3) & 1) * 16;
    const unsigned vB = (unsigned)(((l >> 3) & 1) * 8 + (l & 7)) * 128 + (l >> 4) * 16;

    float oacc[8][4] = {};
    float lacc[4] = {};

    for (int t = 0; t < NS; t++) {
        int buf = t & 1;
        MBAR_WAIT(mb + buf * 8, (t >> 1) & 1);
        unsigned base = sbase + buf * AT_STEP;

        #pragma unroll
        for (int sub = 0; sub < 2; sub++) {
            unsigned so = sub * 8192;

            unsigned sc16[8][2];
            #pragma unroll
            for (int nb = 0; nb < 8; nb++) { sc16[nb][0] = 0u; sc16[nb][1] = 0u; }
            #pragma unroll
            for (int kb = 0; kb < 4; kb++) {
                #pragma unroll
                for (int nbp = 0; nbp < 4; nbp++) {
                    unsigned b0, b1, b2, b3;
                    ldsm_x4(b0, b1, b2, b3, base + swz(kB + so + nbp * 2048 + kb * 32));
                    mma16816h(sc16[nbp * 2],     qa[kb][0], qa[kb][1], qa[kb][2], qa[kb][3], b0, b1);
                    mma16816h(sc16[nbp * 2 + 1], qa[kb][0], qa[kb][1], qa[kb][2], qa[kb][3], b2, b3);
                }
            }

            unsigned pa[4][4];
            #pragma unroll
            for (int kb = 0; kb < 4; kb++) {
                pa[kb][0] = ex2h2(sc16[2 * kb][0]);
                pa[kb][1] = ex2h2(sc16[2 * kb][1]);
                pa[kb][2] = ex2h2(sc16[2 * kb + 1][0]);
                pa[kb][3] = ex2h2(sc16[2 * kb + 1][1]);
            }

            #pragma unroll
            for (int kb = 0; kb < 4; kb++) {
                mma16816(lacc, pa[kb][0], pa[kb][1], pa[kb][2], pa[kb][3], ONES, ONES);
                #pragma unroll
                for (int nbp = 0; nbp < 4; nbp++) {
                    unsigned b0, b1, b2, b3;
                    ldsm_x4t(b0, b1, b2, b3,
                             base + 16384 + swz(vB + so + kb * 2048 + nbp * 32));
                    mma16816(oacc[nbp * 2],     pa[kb][0], pa[kb][1], pa[kb][2], pa[kb][3], b0, b1);
                    mma16816(oacc[nbp * 2 + 1], pa[kb][0], pa[kb][1], pa[kb][2], pa[kb][3], b2, b3);
                }
            }
        }
        __syncthreads();
        if (t + 2 < NS && tid == 0) issue(s0 + t + 2, buf);
    }

    // ---- partial epilogue ----
    float* op = part ? d_o1 : d_o0;
    float* lp = part ? d_l1 : d_l0;
    float* ob = op + ((size_t)bh * SQ + q0 + wq) * HDIM;
    #pragma unroll
    for (int nb = 0; nb < 8; nb++) {
        float2 v0 = {oacc[nb][0], oacc[nb][1]};
        float2 v1 = {oacc[nb][2], oacc[nb][3]};
        *(float2*)&ob[(r0    ) * HDIM + nb * 8 + 2 * m4] = v0;
        *(float2*)&ob[(r0 + 8) * HDIM + nb * 8 + 2 * m4] = v1;
    }
    if (m4 == 0) {
        lp[bh * SQ + q0 + wq + r0]     = lacc[0];
        lp[bh * SQ + q0 + wq + r0 + 8] = lacc[2];
    }
}

// ---------------------------------------------------------------------------
// Combine: out = (O0 + O1) / (l0 + l1), with [bh][q][d] -> [b][q][h*64+d]
// ---------------------------------------------------------------------------
__global__ void combine_kernel(float* __restrict__ out) {
    int i = blockIdx.x * blockDim.x + threadIdx.x;
    int d4 = i & 15;
    int q  = (i >> 4) & (SQ - 1);
    int bh = i >> 15;
    float4 a = ((const float4*)d_o0)[i];
    float4 b = ((const float4*)d_o1)[i];
    float inv = 1.0f / (d_l0[bh * SQ + q] + d_l1[bh * SQ + q]);
    float4 r;
    r.x = (a.x + b.x) * inv;
    r.y = (a.y + b.y) * inv;
    r.z = (a.z + b.z) * inv;
    r.w = (a.w + b.w) * inv;
    int bb = bh >> 4, h = bh & 15;
    ((float4*)out)[(size_t)(bb * SQ + q) * (HIDDEN / 4) + h * 16 + d4] = r;
}

// ---------------------------------------------------------------------------
extern "C" void kernel_launch(void* const* d_in, const int* in_sizes, int n_in,
                              void* d_out, int out_size)
{
    const float* x    = (const float*)d_in[0];
    const float* kvs  = (const float*)d_in[1];
    const float* Wq   = (const float*)d_in[2];
    const float* bq   = (const float*)d_in[3];
    const float* Wk   = (const float*)d_in[4];
    const float* bk   = (const float*)d_in[5];
    const float* Wv   = (const float*)d_in[6];
    const float* bv   = (const float*)d_in[7];
    const float* kvw  = (const float*)d_in[8];
    float* out = (float*)d_out;

    cudaFuncSetAttribute(qkv_kernel, cudaFuncAttributeMaxDynamicSharedMemorySize,
                         QKV_SMEM);
    cudaFuncSetAttribute(attn_kernel, cudaFuncAttributeMaxDynamicSharedMemorySize,
                         ATTN_SMEM);

    cudaStream_t s2;
    cudaStreamCreateWithFlags(&s2, cudaStreamNonBlocking);
    cudaEvent_t evC, evQ, evB;
    cudaEventCreateWithFlags(&evC, cudaEventDisableTiming);
    cudaEventCreateWithFlags(&evQ, cudaEventDisableTiming);
    cudaEventCreateWithFlags(&evB, cudaEventDisableTiming);

    // stream 0: conversions -> Q projection -> attention over kvs keys
    cvt_all_kernel<<<(TOTN4 + 255) / 256, 256>>>(x, Wq, Wk, Wv, kvs, kvw);
    cudaEventRecord(evC, 0);

    dim3 gq(NB * SQ / 64, NHEAD / 2, 1);
    qkv_kernel<<<gq, 256, QKV_SMEM>>>(bq, bk, bv, 0);
    cudaEventRecord(evQ, 0);

    dim3 g2(SQ / 128, NB * NHEAD);
    attn_kernel<<<g2, 256, ATTN_SMEM>>>(0, 16, 0);

    // stream s2: K/V projection -> attention over projected keys
    cudaStreamWaitEvent(s2, evC, 0);
    dim3 gkv(NB * SQ / 64, NHEAD / 2, 2);
    qkv_kernel<<<gkv, 256, QKV_SMEM, s2>>>(bq, bk, bv, 1);
    cudaStreamWaitEvent(s2, evQ, 0);
    attn_kernel<<<g2, 256, ATTN_SMEM, s2>>>(16, 32, 1);
    cudaEventRecord(evB, s2);

    // join and combine
    cudaStreamWaitEvent(0, evB, 0);
    combine_kernel<<<NB * NHEAD * SQ * HDIM / 4 / 256, 256>>>(out);
}

// round 15
// speedup vs baseline: 1.3725x; 1.1401x over previous
#include <cuda_runtime.h>
#include <cuda_fp16.h>
#include <math.h>

#define NB     2
#define SQ     2048
#define HIDDEN 1024
#define NHEAD  16
#define HDIM   64
#define SKVLEN 2048
#define TKV    4096
#define LOG2E  1.4426950408889634f

// half-precision staging buffers (pre-swizzled / tiled where noted)
__device__ __align__(1024) __half d_xh[NB * SQ * HIDDEN];      // [ks][m][64], SW128
__device__ __align__(1024) __half d_wh[3 * HIDDEN * HIDDEN];   // [z][ks][n][64], SW128
__device__ __align__(1024) __half d_kvsh[2 * NB * NHEAD * SKVLEN * HDIM]; // [2][bh][j][64], SW128
__device__ __align__(1024) __half d_qh[NB * NHEAD * SQ * HDIM];  // linear, pre-scaled log2e/64
__device__ __align__(1024) __half d_kh[NB * NHEAD * SQ * HDIM];  // [bh][s][64], SW128
__device__ __align__(1024) __half d_vh[NB * NHEAD * SQ * HDIM];  // [bh][s][64], SW128

// split-attention partial outputs
__device__ float d_o0[NB * NHEAD * SQ * HDIM];
__device__ float d_o1[NB * NHEAD * SQ * HDIM];
__device__ float d_l0[NB * NHEAD * SQ];
__device__ float d_l1[NB * NHEAD * SQ];

// ---------------------------------------------------------------------------
// helpers
// ---------------------------------------------------------------------------
__device__ __forceinline__ unsigned swz(unsigned b) { return b ^ ((b >> 3) & 0x70); }

__device__ __forceinline__ void mma16816(float c[4], unsigned a0, unsigned a1,
                                         unsigned a2, unsigned a3,
                                         unsigned b0, unsigned b1) {
    asm volatile(
        "mma.sync.aligned.m16n8k16.row.col.f32.f16.f16.f32 "
        "{%0,%1,%2,%3},{%4,%5,%6,%7},{%8,%9},{%0,%1,%2,%3};"
        : "+f"(c[0]), "+f"(c[1]), "+f"(c[2]), "+f"(c[3])
        : "r"(a0), "r"(a1), "r"(a2), "r"(a3), "r"(b0), "r"(b1));
}
__device__ __forceinline__ void mma16816h(unsigned c[2], unsigned a0, unsigned a1,
                                          unsigned a2, unsigned a3,
                                          unsigned b0, unsigned b1) {
    asm volatile(
        "mma.sync.aligned.m16n8k16.row.col.f16.f16.f16.f16 "
        "{%0,%1},{%2,%3,%4,%5},{%6,%7},{%0,%1};"
        : "+r"(c[0]), "+r"(c[1])
        : "r"(a0), "r"(a1), "r"(a2), "r"(a3), "r"(b0), "r"(b1));
}
__device__ __forceinline__ void ldsm_x4(unsigned& r0, unsigned& r1,
                                        unsigned& r2, unsigned& r3, unsigned a) {
    asm volatile("ldmatrix.sync.aligned.m8n8.x4.shared.b16 {%0,%1,%2,%3},[%4];"
                 : "=r"(r0), "=r"(r1), "=r"(r2), "=r"(r3) : "r"(a));
}
__device__ __forceinline__ void ldsm_x4t(unsigned& r0, unsigned& r1,
                                         unsigned& r2, unsigned& r3, unsigned a) {
    asm volatile("ldmatrix.sync.aligned.m8n8.x4.trans.shared.b16 {%0,%1,%2,%3},[%4];"
                 : "=r"(r0), "=r"(r1), "=r"(r2), "=r"(r3) : "r"(a));
}
__device__ __forceinline__ unsigned ex2h2(unsigned x) {
    unsigned r;
    asm("ex2.approx.f16x2 %0, %1;" : "=r"(r) : "r"(x));
    return r;
}
__device__ __forceinline__ void bulk_g2s(unsigned dst, const void* src,
                                         unsigned bytes, unsigned mbar) {
    asm volatile(
        "cp.async.bulk.shared::cluster.global.mbarrier::complete_tx::bytes "
        "[%0], [%1], %2, [%3];"
        :: "r"(dst), "l"(src), "r"(bytes), "r"(mbar) : "memory");
}
#define MBAR_INIT(mb, n) \
    asm volatile("mbarrier.init.shared.b64 [%0], %1;" :: "r"(mb), "r"((unsigned)(n)) : "memory")
#define MBAR_EXPECT_TX(mb, bytes) \
    asm volatile("mbarrier.arrive.expect_tx.shared.b64 _, [%0], %1;" \
                 :: "r"(mb), "r"((unsigned)(bytes)) : "memory")
#define MBAR_WAIT(mb, par) do { \
    unsigned _d; \
    asm volatile("{\n\t.reg .pred p;\n\t" \
        "mbarrier.try_wait.parity.acquire.cta.shared::cta.b64 p, [%1], %2;\n\t" \
        "selp.b32 %0, 1, 0, p;\n\t}" : "=r"(_d) : "r"(mb), "r"((unsigned)(par)) : "memory"); \
    if (!_d) { \
        asm volatile("{\n\t.reg .pred P1;\n\tWL_%=:\n\t" \
            "mbarrier.try_wait.parity.acquire.cta.shared::cta.b64 P1, [%0], %1, 0x989680;\n\t" \
            "@P1 bra.uni WD_%=;\n\tbra.uni WL_%=;\n\tWD_%=:\n\t}" \
            :: "r"(mb), "r"((unsigned)(par)) : "memory"); \
    } \
} while (0)

// ---------------------------------------------------------------------------
// Conversions.  Split: x+W (needed by projections) vs kvs (needed by attnA).
// ---------------------------------------------------------------------------
#define XN4   (NB * SQ * HIDDEN / 4)
#define WN4   (HIDDEN * HIDDEN / 4)
#define KVN4  (2 * NB * NHEAD * SKVLEN * HDIM / 4)
#define XWN4  (XN4 + 3 * WN4)

__global__ void cvt_xw_kernel(const float* __restrict__ x,
                              const float* __restrict__ Wq,
                              const float* __restrict__ Wk,
                              const float* __restrict__ Wv) {
    int j = blockIdx.x * blockDim.x + threadIdx.x;
    if (j >= XWN4) return;
    if (j < XN4) {
        float4 v = reinterpret_cast<const float4*>(x)[j];
        int m = j >> 8, k4 = (j & 255) * 4;
        unsigned hidx = (unsigned)(k4 >> 6) * (NB * SQ * 64u) + (unsigned)m * 64 + (k4 & 63);
        unsigned b = swz(hidx * 2);
        char* p = (char*)d_xh;
        *(__half2*)(p + b)     = __floats2half2_rn(v.x, v.y);
        *(__half2*)(p + b + 4) = __floats2half2_rn(v.z, v.w);
    } else {
        int jj = j - XN4;
        int z = jj / WN4;
        jj -= z * WN4;
        const float* W = (z == 0) ? Wq : (z == 1) ? Wk : Wv;
        float4 v = reinterpret_cast<const float4*>(W)[jj];
        int n = jj >> 8, k4 = (jj & 255) * 4;
        unsigned hidx = ((unsigned)(z * 16 + (k4 >> 6))) * 65536u + (unsigned)n * 64 + (k4 & 63);
        unsigned b = swz(hidx * 2);
        char* p = (char*)d_wh;
        *(__half2*)(p + b)     = __floats2half2_rn(v.x, v.y);
        *(__half2*)(p + b + 4) = __floats2half2_rn(v.z, v.w);
    }
}

__global__ void cvt_kvs_kernel(const float* __restrict__ kvs,
                               const float* __restrict__ kvw) {
    int j = blockIdx.x * blockDim.x + threadIdx.x;
    if (j >= KVN4) return;
    float s = kvw[0];
    float4 v = reinterpret_cast<const float4*>(kvs)[j];
    unsigned b = swz((unsigned)j * 8u);
    char* p = (char*)d_kvsh;
    *(__half2*)(p + b)     = __floats2half2_rn(v.x * s, v.y * s);
    *(__half2*)(p + b + 4) = __floats2half2_rn(v.z * s, v.w * s);
}

// ---------------------------------------------------------------------------
// QKV projection: y = x @ W^T + b.  fp16 mma, fp32 accum, bulk-copy staging.
// grid = (64, 8, nz), block = 128 (4 warps).  CTA tile m64 x n128 x k64 stage.
// Warp tile m32 x n64.
// ---------------------------------------------------------------------------
#define QKV_STEP 24576
#define QKV_MB   (2 * QKV_STEP)
#define QKV_SMEM (QKV_MB + 16)

__global__ __launch_bounds__(128, 2)
void qkv_kernel(const float* __restrict__ bq, const float* __restrict__ bk,
                const float* __restrict__ bv, int zbase)
{
    extern __shared__ __align__(128) char sm[];

    const int z = zbase + blockIdx.z;
    const float* __restrict__ bias = (z == 0) ? bq : (z == 1) ? bk : bv;
    const float scl = (z == 0) ? (LOG2E / 64.0f) : 1.0f;

    const int m0 = blockIdx.x * 64;
    const int n0 = blockIdx.y * 128;
    const int tid = threadIdx.x, lane = tid & 31, w = tid >> 5;
    const int wm = w >> 1, wn = w & 1;
    const int l = lane;

    unsigned sbase;
    asm("{ .reg .u64 t; cvta.to.shared.u64 t, %1; cvt.u32.u64 %0, t; }" : "=r"(sbase) : "l"(sm));
    const unsigned mb = sbase + QKV_MB;

    auto issue = [&](int ks, int buf) {
        unsigned d = sbase + buf * QKV_STEP;
        unsigned m = mb + buf * 8;
        MBAR_EXPECT_TX(m, QKV_STEP);
        bulk_g2s(d,        d_xh + ((size_t)ks * (NB * SQ) + m0) * 64, 8192, m);
        bulk_g2s(d + 8192, d_wh + (((size_t)z * 16 + ks) * 1024 + n0) * 64, 16384, m);
    };

    if (tid == 0) { MBAR_INIT(mb, 1); MBAR_INIT(mb + 8, 1); }
    __syncthreads();
    if (tid == 0) { issue(0, 0); issue(1, 1); }

    const unsigned aB = (unsigned)(wm * 32 + (l & 15)) * 128 + (l >> 4) * 16;  // +2048 for m-block 1
    const unsigned bB = (unsigned)(wn * 64 + (l >> 4) * 8 + (l & 7)) * 128 + ((l >> 3) & 1) * 16;

    float acc[2][8][4] = {};

    for (int ks = 0; ks < 16; ks++) {
        int buf = ks & 1;
        MBAR_WAIT(mb + buf * 8, (ks >> 1) & 1);
        unsigned base = sbase + buf * QKV_STEP;

        #pragma unroll
        for (int kb = 0; kb < 4; kb++) {
            unsigned a0[4], a1[4];
            ldsm_x4(a0[0], a0[1], a0[2], a0[3], base + swz(aB + kb * 32));
            ldsm_x4(a1[0], a1[1], a1[2], a1[3], base + swz(aB + 2048 + kb * 32));
            #pragma unroll
            for (int nbp = 0; nbp < 4; nbp++) {
                unsigned b0, b1, b2, b3;
                ldsm_x4(b0, b1, b2, b3, base + 8192 + swz(bB + nbp * 2048 + kb * 32));
                mma16816(acc[0][nbp * 2],     a0[0], a0[1], a0[2], a0[3], b0, b1);
                mma16816(acc[0][nbp * 2 + 1], a0[0], a0[1], a0[2], a0[3], b2, b3);
                mma16816(acc[1][nbp * 2],     a1[0], a1[1], a1[2], a1[3], b0, b1);
                mma16816(acc[1][nbp * 2 + 1], a1[0], a1[1], a1[2], a1[3], b2, b3);
            }
        }
        __syncthreads();
        if (ks + 2 < 16 && tid == 0) issue(ks + 2, buf);
    }

    const int h = blockIdx.y * 2 + wn;
    #pragma unroll
    for (int i = 0; i < 2; i++) {
        const int mlo = m0 + wm * 32 + i * 16 + (lane >> 2);
        #pragma unroll
        for (int nb = 0; nb < 8; nb++) {
            int dcol = nb * 8 + 2 * (lane & 3);
            float2 bv2 = *(const float2*)&bias[h * 64 + dcol];
            __half2 h0 = __floats2half2_rn((acc[i][nb][0] + bv2.x) * scl,
                                           (acc[i][nb][1] + bv2.y) * scl);
            __half2 h1 = __floats2half2_rn((acc[i][nb][2] + bv2.x) * scl,
                                           (acc[i][nb][3] + bv2.y) * scl);
            int m1 = mlo, m2 = mlo + 8;
            if (z == 0) {
                *(__half2*)&d_qh[(((size_t)(m1 >> 11) * NHEAD + h) * SQ + (m1 & 2047)) * HDIM + dcol] = h0;
                *(__half2*)&d_qh[(((size_t)(m2 >> 11) * NHEAD + h) * SQ + (m2 & 2047)) * HDIM + dcol] = h1;
            } else {
                char* p = (char*)((z == 1) ? d_kh : d_vh);
                unsigned i1 = (((unsigned)(m1 >> 11) * NHEAD + h) * SQ + (m1 & 2047)) * 64 + dcol;
                unsigned i2 = (((unsigned)(m2 >> 11) * NHEAD + h) * SQ + (m2 & 2047)) * 64 + dcol;
                *(__half2*)(p + swz(i1 * 2)) = h0;
                *(__half2*)(p + swz(i2 * 2)) = h1;
            }
        }
    }
}

// ---------------------------------------------------------------------------
// Flash attention (split): key stages [s0, s1) of 128 keys; bulk staging.
// grid = (16, 32), block = 128 (4 warps x m32 q-rows), q-tile 128.
// ---------------------------------------------------------------------------
#define AT_STEP  32768
#define AT_MB    (2 * AT_STEP)
#define ATTN_SMEM (AT_MB + 16)

__global__ __launch_bounds__(128, 2)
void attn_kernel(int s0, int s1, int part)
{
    extern __shared__ __align__(128) char sm[];

    const int tid = threadIdx.x, lane = tid & 31, w = tid >> 5;
    const int r0 = lane >> 2, m4 = lane & 3;
    const int wq = w * 32;
    const int q0 = blockIdx.x * 128;
    const int bh = blockIdx.y;
    const int l = lane;
    const int NS = s1 - s0;

    unsigned sbase;
    asm("{ .reg .u64 t; cvta.to.shared.u64 t, %1; cvt.u32.u64 %0, t; }" : "=r"(sbase) : "l"(sm));
    const unsigned mb = sbase + AT_MB;
    const unsigned ONES = 0x3C003C00u;

    // Q fragments, 2 m-blocks of 16 (linear layout, pre-scaled by log2e/64)
    unsigned qa[2][4][4];
    #pragma unroll
    for (int i = 0; i < 2; i++) {
        const __half* qb = d_qh + ((size_t)bh * SQ + q0 + wq + i * 16) * HDIM;
        #pragma unroll
        for (int kb = 0; kb < 4; kb++) {
            qa[i][kb][0] = *(const unsigned*)&qb[(r0    ) * 64 + kb * 16 + 2 * m4    ];
            qa[i][kb][1] = *(const unsigned*)&qb[(r0 + 8) * 64 + kb * 16 + 2 * m4    ];
            qa[i][kb][2] = *(const unsigned*)&qb[(r0    ) * 64 + kb * 16 + 2 * m4 + 8];
            qa[i][kb][3] = *(const unsigned*)&qb[(r0 + 8) * 64 + kb * 16 + 2 * m4 + 8];
        }
    }

    auto issue = [&](int st, int buf) {
        const __half *ks_p, *vs_p;
        if (st < 16) {
            ks_p = d_kvsh + ((size_t)bh * SKVLEN + st * 128) * 64;
            vs_p = d_kvsh + ((size_t)(NB * NHEAD + bh) * SKVLEN + st * 128) * 64;
        } else {
            int js = (st - 16) * 128;
            ks_p = d_kh + ((size_t)bh * SQ + js) * 64;
            vs_p = d_vh + ((size_t)bh * SQ + js) * 64;
        }
        unsigned d = sbase + buf * AT_STEP;
        unsigned m = mb + buf * 8;
        MBAR_EXPECT_TX(m, AT_STEP);
        bulk_g2s(d,         ks_p, 16384, m);
        bulk_g2s(d + 16384, vs_p, 16384, m);
    };

    if (tid == 0) { MBAR_INIT(mb, 1); MBAR_INIT(mb + 8, 1); }
    __syncthreads();
    if (tid == 0) { issue(s0, 0); issue(s0 + 1, 1); }

    const unsigned kB = (unsigned)((l >> 4) * 8 + (l & 7)) * 128 + ((l >> 3) & 1) * 16;
    const unsigned vB = (unsigned)(((l >> 3) & 1) * 8 + (l & 7)) * 128 + (l >> 4) * 16;

    float oacc[2][8][4] = {};
    float lacc[2][4] = {};

    for (int t = 0; t < NS; t++) {
        int buf = t & 1;
        MBAR_WAIT(mb + buf * 8, (t >> 1) & 1);
        unsigned base = sbase + buf * AT_STEP;

        #pragma unroll
        for (int sub = 0; sub < 2; sub++) {
            unsigned so = sub * 8192;

            unsigned sc16[2][8][2];
            #pragma unroll
            for (int i = 0; i < 2; i++)
                #pragma unroll
                for (int nb = 0; nb < 8; nb++) { sc16[i][nb][0] = 0u; sc16[i][nb][1] = 0u; }
            #pragma unroll
            for (int kb = 0; kb < 4; kb++) {
                #pragma unroll
                for (int nbp = 0; nbp < 4; nbp++) {
                    unsigned b0, b1, b2, b3;
                    ldsm_x4(b0, b1, b2, b3, base + swz(kB + so + nbp * 2048 + kb * 32));
                    mma16816h(sc16[0][nbp * 2],     qa[0][kb][0], qa[0][kb][1], qa[0][kb][2], qa[0][kb][3], b0, b1);
                    mma16816h(sc16[0][nbp * 2 + 1], qa[0][kb][0], qa[0][kb][1], qa[0][kb][2], qa[0][kb][3], b2, b3);
                    mma16816h(sc16[1][nbp * 2],     qa[1][kb][0], qa[1][kb][1], qa[1][kb][2], qa[1][kb][3], b0, b1);
                    mma16816h(sc16[1][nbp * 2 + 1], qa[1][kb][0], qa[1][kb][1], qa[1][kb][2], qa[1][kb][3], b2, b3);
                }
            }

            unsigned pa[2][4][4];
            #pragma unroll
            for (int i = 0; i < 2; i++)
                #pragma unroll
                for (int kb = 0; kb < 4; kb++) {
                    pa[i][kb][0] = ex2h2(sc16[i][2 * kb][0]);
                    pa[i][kb][1] = ex2h2(sc16[i][2 * kb][1]);
                    pa[i][kb][2] = ex2h2(sc16[i][2 * kb + 1][0]);
                    pa[i][kb][3] = ex2h2(sc16[i][2 * kb + 1][1]);
                }

            #pragma unroll
            for (int kb = 0; kb < 4; kb++) {
                mma16816(lacc[0], pa[0][kb][0], pa[0][kb][1], pa[0][kb][2], pa[0][kb][3], ONES, ONES);
                mma16816(lacc[1], pa[1][kb][0], pa[1][kb][1], pa[1][kb][2], pa[1][kb][3], ONES, ONES);
                #pragma unroll
                for (int nbp = 0; nbp < 4; nbp++) {
                    unsigned b0, b1, b2, b3;
                    ldsm_x4t(b0, b1, b2, b3,
                             base + 16384 + swz(vB + so + kb * 2048 + nbp * 32));
                    mma16816(oacc[0][nbp * 2],     pa[0][kb][0], pa[0][kb][1], pa[0][kb][2], pa[0][kb][3], b0, b1);
                    mma16816(oacc[0][nbp * 2 + 1], pa[0][kb][0], pa[0][kb][1], pa[0][kb][2], pa[0][kb][3], b2, b3);
                    mma16816(oacc[1][nbp * 2],     pa[1][kb][0], pa[1][kb][1], pa[1][kb][2], pa[1][kb][3], b0, b1);
                    mma16816(oacc[1][nbp * 2 + 1], pa[1][kb][0], pa[1][kb][1], pa[1][kb][2], pa[1][kb][3], b2, b3);
                }
            }
        }
        __syncthreads();
        if (t + 2 < NS && tid == 0) issue(s0 + t + 2, buf);
    }

    // ---- partial epilogue ----
    float* op = part ? d_o1 : d_o0;
    float* lp = part ? d_l1 : d_l0;
    #pragma unroll
    for (int i = 0; i < 2; i++) {
        float* ob = op + ((size_t)bh * SQ + q0 + wq + i * 16) * HDIM;
        #pragma unroll
        for (int nb = 0; nb < 8; nb++) {
            float2 v0 = {oacc[i][nb][0], oacc[i][nb][1]};
            float2 v1 = {oacc[i][nb][2], oacc[i][nb][3]};
            *(float2*)&ob[(r0    ) * HDIM + nb * 8 + 2 * m4] = v0;
            *(float2*)&ob[(r0 + 8) * HDIM + nb * 8 + 2 * m4] = v1;
        }
        if (m4 == 0) {
            lp[bh * SQ + q0 + wq + i * 16 + r0]     = lacc[i][0];
            lp[bh * SQ + q0 + wq + i * 16 + r0 + 8] = lacc[i][2];
        }
    }
}

// ---------------------------------------------------------------------------
// Combine: out = (O0 + O1) / (l0 + l1), with [bh][q][d] -> [b][q][h*64+d]
// ---------------------------------------------------------------------------
__global__ void combine_kernel(float* __restrict__ out) {
    int i = blockIdx.x * blockDim.x + threadIdx.x;
    int d4 = i & 15;
    int q  = (i >> 4) & (SQ - 1);
    int bh = i >> 15;
    float4 a = ((const float4*)d_o0)[i];
    float4 b = ((const float4*)d_o1)[i];
    float inv = 1.0f / (d_l0[bh * SQ + q] + d_l1[bh * SQ + q]);
    float4 r;
    r.x = (a.x + b.x) * inv;
    r.y = (a.y + b.y) * inv;
    r.z = (a.z + b.z) * inv;
    r.w = (a.w + b.w) * inv;
    int bb = bh >> 4, h = bh & 15;
    ((float4*)out)[(size_t)(bb * SQ + q) * (HIDDEN / 4) + h * 16 + d4] = r;
}

// ---------------------------------------------------------------------------
extern "C" void kernel_launch(void* const* d_in, const int* in_sizes, int n_in,
                              void* d_out, int out_size)
{
    const float* x    = (const float*)d_in[0];
    const float* kvs  = (const float*)d_in[1];
    const float* Wq   = (const float*)d_in[2];
    const float* bq   = (const float*)d_in[3];
    const float* Wk   = (const float*)d_in[4];
    const float* bk   = (const float*)d_in[5];
    const float* Wv   = (const float*)d_in[6];
    const float* bv   = (const float*)d_in[7];
    const float* kvw  = (const float*)d_in[8];
    float* out = (float*)d_out;

    cudaFuncSetAttribute(qkv_kernel, cudaFuncAttributeMaxDynamicSharedMemorySize,
                         QKV_SMEM);
    cudaFuncSetAttribute(attn_kernel, cudaFuncAttributeMaxDynamicSharedMemorySize,
                         ATTN_SMEM);

    // ONE side stream (r12-proven footprint; two streams tripped the
    // teardown memory check in r14).
    cudaStream_t s2;
    cudaStreamCreateWithFlags(&s2, cudaStreamNonBlocking);
    cudaEvent_t evRoot, evXW, evQ, evKVS, evB;
    cudaEventCreateWithFlags(&evRoot, cudaEventDisableTiming);
    cudaEventCreateWithFlags(&evXW, cudaEventDisableTiming);
    cudaEventCreateWithFlags(&evQ, cudaEventDisableTiming);
    cudaEventCreateWithFlags(&evKVS, cudaEventDisableTiming);
    cudaEventCreateWithFlags(&evB, cudaEventDisableTiming);

    // Fork: s2 joins the capture graph via a root event BEFORE any launch.
    cudaEventRecord(evRoot, 0);
    cudaStreamWaitEvent(s2, evRoot, 0);

    // s2: kvs conversion (concurrent with cvt_xw) -> KV proj -> attnB
    cvt_kvs_kernel<<<(KVN4 + 255) / 256, 256, 0, s2>>>(kvs, kvw);
    cudaEventRecord(evKVS, s2);

    // s0: x+W conversion -> Q projection -> attnA (kvs keys; waits on evKVS)
    cvt_xw_kernel<<<(XWN4 + 255) / 256, 256>>>(x, Wq, Wk, Wv);
    cudaEventRecord(evXW, 0);

    dim3 gq(NB * SQ / 64, NHEAD / 2, 1);
    qkv_kernel<<<gq, 128, QKV_SMEM>>>(bq, bk, bv, 0);
    cudaEventRecord(evQ, 0);

    cudaStreamWaitEvent(0, evKVS, 0);
    dim3 g2(SQ / 128, NB * NHEAD);
    attn_kernel<<<g2, 128, ATTN_SMEM>>>(0, 16, 0);

    // s2 (cont.): K/V projection (needs x+W) -> attnB (needs Q too)
    cudaStreamWaitEvent(s2, evXW, 0);
    dim3 gkv(NB * SQ / 64, NHEAD / 2, 2);
    qkv_kernel<<<gkv, 128, QKV_SMEM, s2>>>(bq, bk, bv, 1);
    cudaStreamWaitEvent(s2, evQ, 0);
    attn_kernel<<<g2, 128, ATTN_SMEM, s2>>>(16, 32, 1);
    cudaEventRecord(evB, s2);

    // join and combine
    cudaStreamWaitEvent(0, evB, 0);
    combine_kernel<<<NB * NHEAD * SQ * HDIM / 4 / 256, 256>>>(out);
}